// round 2
// baseline (speedup 1.0000x reference)
#include <cuda_runtime.h>
#include <cstdint>

// Correlation D=4, S1=S2=1 ; x1,x2:(4,128,256,256) f32 ; out:(4,81,256,256) f32
//
// Block = (4,8,9) = 288 threads, tile 8 rows x 32 cols, all 81 displacements.
// Thread (wg,ty,ky): 8 consecutive pixels, one ky, all 9 kx -> 72 fp32 accs
// held as 36 f32x2 pairs, updated with fma.rn.f32x2 (FFMA2).
// Channels staged through smem (CB=8/stage), 3-buffer cp.async ring,
// one __syncthreads per stage. Loader indices hoisted out of the stage loop.

#define Himg 256
#define Wimg 256
#define Cimg 128
#define TH 8
#define TW 32
#define PPT 8
#define CB 8
#define NSTAGE 16
#define S1F 34                    // x1 smem row stride (floats), conflict-free
#define S2F 50                    // x2 smem row stride (floats), conflict-free
#define X1_STAGE (CB*TH*S1F)      // 2176 floats
#define X2_STAGE (CB*16*S2F)      // 6400 floats
#define X1_STAGE_B (X1_STAGE*4)
#define X2_STAGE_B (X2_STAGE*4)
#define SMEM_BYTES (3*(X1_STAGE_B + X2_STAGE_B))   // 102912 B
#define CSTRIDE (CB*Himg*Wimg)    // gmem float advance per stage

typedef unsigned long long ull;

__device__ __forceinline__ void cp_async8(uint32_t dst, const float* src, int sz) {
    asm volatile("cp.async.ca.shared.global [%0], [%1], 8, %2;\n"
                 :: "r"(dst), "l"(src), "r"(sz) : "memory");
}
__device__ __forceinline__ void cp_commit() {
    asm volatile("cp.async.commit_group;\n" ::: "memory");
}
__device__ __forceinline__ ull ffma2(ull a, ull b, ull c) {
    ull d;
    asm("fma.rn.f32x2 %0, %1, %2, %3;" : "=l"(d) : "l"(a), "l"(b), "l"(c));
    return d;
}
// {hi(e0), lo(e1)} as packed f32x2
__device__ __forceinline__ ull oddpair(ull e0, ull e1) {
    ull r;
    asm("mov.b64 %0, {%1, %2};" : "=l"(r)
        : "r"((unsigned)(e0 >> 32)), "r"((unsigned)e1));
    return r;
}
__device__ __forceinline__ float f2lo(ull a) { return __uint_as_float((unsigned)a); }
__device__ __forceinline__ float f2hi(ull a) { return __uint_as_float((unsigned)(a >> 32)); }

__device__ __forceinline__ void load_stage(bool is_loader,
                                           const float* s2, const float* s1,
                                           uint32_t d2, uint32_t d1,
                                           int szm, int szlo, int szhi) {
    if (is_loader) {
        cp_async8(d2 + 0,  s2 + 0,  szlo);
        cp_async8(d2 + 8,  s2 + 2,  szlo);
        cp_async8(d2 + 16, s2 + 4,  szm);
        cp_async8(d2 + 24, s2 + 6,  szm);
        cp_async8(d2 + 32, s2 + 8,  szm);
        cp_async8(d2 + 40, s2 + 10, szm);
        cp_async8(d2 + 48, s2 + 12, szm);
        cp_async8(d2 + 56, s2 + 14, szm);
        cp_async8(d2 + 64, s2 + 16, szhi);
        cp_async8(d2 + 72, s2 + 18, szhi);
        cp_async8(d1 + 0,  s1 + 0, 8);
        cp_async8(d1 + 8,  s1 + 2, 8);
        cp_async8(d1 + 16, s1 + 4, 8);
        cp_async8(d1 + 24, s1 + 6, 8);
    }
    cp_commit();
}

__device__ __forceinline__ void compute_stage(const float* x1b, const float* x2b,
                                              ull acc[4][9]) {
    #pragma unroll
    for (int c = 0; c < CB; ++c) {
        const ull* ap = reinterpret_cast<const ull*>(x1b + c * (TH * S1F));
        const ull* vp = reinterpret_cast<const ull*>(x2b + c * (16 * S2F));
        ull A[4], E[8], O[7];
        #pragma unroll
        for (int j = 0; j < 4; ++j) A[j] = ap[j];
        #pragma unroll
        for (int j = 0; j < 8; ++j) E[j] = vp[j];
        #pragma unroll
        for (int j = 0; j < 7; ++j) O[j] = oddpair(E[j], E[j + 1]);
        #pragma unroll
        for (int pp = 0; pp < 4; ++pp) {
            #pragma unroll
            for (int kx = 0; kx < 9; ++kx) {
                ull b = (kx & 1) ? O[pp + ((kx - 1) >> 1)] : E[pp + (kx >> 1)];
                acc[pp][kx] = ffma2(A[pp], b, acc[pp][kx]);
            }
        }
    }
}

__global__ void __launch_bounds__(288, 1)
corr_kernel(const float* __restrict__ x1, const float* __restrict__ x2,
            float* __restrict__ out) {
    const int wg = threadIdx.x;                 // 0..3 : 8-pixel group
    const int ty = threadIdx.y;                 // 0..7 : row in tile
    const int ky = threadIdx.z;                 // 0..8 : displacement row
    const int tid = wg + (ty << 2) + (ky << 5); // lane = wg + 4*ty per warp

    const int w0 = blockIdx.x * TW;
    const int h0 = blockIdx.y * TH;
    const int n  = blockIdx.z;

    extern __shared__ float sm[];
    const uint32_t smem_u = (uint32_t)__cvta_generic_to_shared(sm);

    const float* x1n = x1 + (size_t)n * Cimg * Himg * Wimg;
    const float* x2n = x2 + (size_t)n * Cimg * Himg * Wimg;

    // ---------- loader setup (hoisted, once) ----------
    const bool is_loader = (tid < 256);
    const int li   = tid & 255;
    const int c2   = li >> 5;          // channel-in-stage 0..7
    const int rr   = (li >> 1) & 15;   // x2 halo row 0..15
    const int half = li & 1;           // 10-chunk half of x2 row
    const int hr   = h0 - 4 + rr;
    const int row_ok = ((unsigned)hr < (unsigned)Himg) ? 1 : 0;
    const int hrc  = row_ok ? hr : 0;
    const float* s2 = x2n + ((size_t)(c2 * Himg + hrc)) * Wimg + (w0 - 4) + half * 20;
    const int szm  = row_ok * 8;
    const int szlo = (half == 0 && w0 == 0) ? 0 : szm;
    const int szhi = (half == 1 && w0 == (Wimg - TW)) ? 0 : szm;
    const int r1 = (li >> 2) & 7;
    const int q  = li & 3;
    const float* s1 = x1n + ((size_t)(c2 * Himg + h0 + r1)) * Wimg + w0 + q * 8;
    const uint32_t d2b = smem_u + 3 * X1_STAGE_B + ((c2 * 16 + rr) * S2F + half * 20) * 4;
    const uint32_t d1b = smem_u + ((c2 * TH + r1) * S1F + q * 8) * 4;

    // ---------- compute-side base pointers ----------
    const float* x1rb = sm + ty * S1F + wg * PPT;
    const float* x2rb = sm + 3 * X1_STAGE + (ty + ky) * S2F + wg * PPT;

    ull acc[4][9];
    #pragma unroll
    for (int pp = 0; pp < 4; ++pp)
        #pragma unroll
        for (int kx = 0; kx < 9; ++kx) acc[pp][kx] = 0ull;

    // ---------- prologue: fill 2 of 3 ring buffers ----------
    load_stage(is_loader, s2, s1, d2b, d1b, szm, szlo, szhi);
    s2 += CSTRIDE; s1 += CSTRIDE;
    load_stage(is_loader, s2, s1, d2b + X2_STAGE_B, d1b + X1_STAGE_B, szm, szlo, szhi);
    s2 += CSTRIDE; s1 += CSTRIDE;

    int bufl = 2;   // load target buffer for stage s+2
    int bufc = 0;   // compute buffer for stage s

    #pragma unroll 1
    for (int s = 0; s < NSTAGE; ++s) {
        if (s < NSTAGE - 1) asm volatile("cp.async.wait_group 1;\n" ::: "memory");
        else                asm volatile("cp.async.wait_group 0;\n" ::: "memory");
        __syncthreads();
        if (s < NSTAGE - 2) {
            load_stage(is_loader, s2, s1,
                       d2b + bufl * X2_STAGE_B, d1b + bufl * X1_STAGE_B,
                       szm, szlo, szhi);
            s2 += CSTRIDE; s1 += CSTRIDE;
            bufl = (bufl == 2) ? 0 : bufl + 1;
        }
        compute_stage(x1rb + bufc * X1_STAGE, x2rb + bufc * X2_STAGE, acc);
        bufc = (bufc == 2) ? 0 : bufc + 1;
    }

    // ---------- epilogue ----------
    const float inv = 1.0f / (float)Cimg;
    float* op = out + ((size_t)(n * 81 + ky * 9) * (Himg * Wimg))
                    + (size_t)(h0 + ty) * Wimg + w0 + wg * PPT;
    #pragma unroll
    for (int kx = 0; kx < 9; ++kx) {
        float4 r0, r1v;
        r0.x  = f2lo(acc[0][kx]) * inv;  r0.y  = f2hi(acc[0][kx]) * inv;
        r0.z  = f2lo(acc[1][kx]) * inv;  r0.w  = f2hi(acc[1][kx]) * inv;
        r1v.x = f2lo(acc[2][kx]) * inv;  r1v.y = f2hi(acc[2][kx]) * inv;
        r1v.z = f2lo(acc[3][kx]) * inv;  r1v.w = f2hi(acc[3][kx]) * inv;
        *reinterpret_cast<float4*>(op + (size_t)kx * (Himg * Wimg))     = r0;
        *reinterpret_cast<float4*>(op + (size_t)kx * (Himg * Wimg) + 4) = r1v;
    }
}

extern "C" void kernel_launch(void* const* d_in, const int* in_sizes, int n_in,
                              void* d_out, int out_size) {
    const float* x1 = (const float*)d_in[0];
    const float* x2 = (const float*)d_in[1];
    float* out = (float*)d_out;

    cudaFuncSetAttribute(corr_kernel, cudaFuncAttributeMaxDynamicSharedMemorySize,
                         SMEM_BYTES);

    dim3 block(4, 8, 9);                 // 288 threads, warp = (wg,ty) for one ky
    dim3 grid(Wimg / TW, Himg / TH, 4);  // 8 x 32 x 4 = 1024 blocks
    corr_kernel<<<grid, block, SMEM_BYTES>>>(x1, x2, out);
}